// round 15
// baseline (speedup 1.0000x reference)
#include <cuda_runtime.h>
#include <cuda_fp16.h>
#include <math.h>

#define NNODES 50000
#define NADJ   6
#define NEDGE  800000
#define NH     256
#define LN_EPS 1e-5f

#define SCAN_B 1024
#define BLK_PER_ADJ ((NNODES + SCAN_B - 1) / SCAN_B)   // 49

// ---------------- device scratch (no allocations allowed) ----------------
static __device__ __align__(16) __half g_state0[(size_t)NNODES * NH];
static __device__ __align__(16) __half g_state1[(size_t)NNODES * NH];
static __device__ __align__(16) __half g_state2[(size_t)NNODES * NH];
static __device__ int   g_cnt[NADJ * NNODES];
static __device__ int   g_rowptr[NADJ * (NNODES + 1)];
static __device__ int   g_cur[NADJ * NNODES];
static __device__ int   g_blksum[NADJ * BLK_PER_ADJ];
static __device__ __align__(16) int2 g_edge[(size_t)NADJ * NEDGE];  // {col, val bits}
static __device__ int   g_adj_idx[6];   // [seq0,seq1,seq2,res0,res1,res2]
static __device__ int   g_used[NADJ];

// ---------------- idx decode: int32 vs int64 autodetect -------------------
__global__ void decode_idx_kernel(const int* __restrict__ seq_raw,
                                  const int* __restrict__ res_raw) {
    if (threadIdx.x != 0 || blockIdx.x != 0) return;
    long long a[6];
    int b[6];
    bool v64 = true, v32 = true;
    const long long* s64 = (const long long*)seq_raw;
    const long long* r64 = (const long long*)res_raw;
#pragma unroll
    for (int i = 0; i < 3; i++) {
        long long t = s64[i]; a[i] = t;     if (t < 0 || t >= NADJ) v64 = false;
        long long u = r64[i]; a[3 + i] = u; if (u < 0 || u >= NADJ) v64 = false;
        int p = seq_raw[i]; b[i] = p;       if (p < 0 || p >= NADJ) v32 = false;
        int q = res_raw[i]; b[3 + i] = q;   if (q < 0 || q >= NADJ) v32 = false;
    }
    (void)v32;
#pragma unroll
    for (int i = 0; i < NADJ; i++) g_used[i] = 0;
#pragma unroll
    for (int i = 0; i < 6; i++) {
        int v = v64 ? (int)a[i] : b[i];
        g_adj_idx[i] = v;
        g_used[v] = 1;
    }
}

// ---------------- CSR build --------------------------------------------
__global__ void zero_cnt_kernel() {
    int i = blockIdx.x * blockDim.x + threadIdx.x;
    if (i < NADJ * NNODES) g_cnt[i] = 0;
}

// 4 edges per thread (NEDGE % 4 == 0, so all 4 share an adjacency)
__global__ void hist_kernel(const int4* __restrict__ rows4) {
    int i = blockIdx.x * blockDim.x + threadIdx.x;
    if (i >= NADJ * NEDGE / 4) return;
    int adj = (i * 4) / NEDGE;
    if (!g_used[adj]) return;
    int4 r = __ldg(rows4 + i);
    int* cnt = g_cnt + adj * NNODES;
    atomicAdd(cnt + r.x, 1);
    atomicAdd(cnt + r.y, 1);
    atomicAdd(cnt + r.z, 1);
    atomicAdd(cnt + r.w, 1);
}

__global__ __launch_bounds__(SCAN_B) void scanA_kernel() {
    __shared__ int s[SCAN_B];
    int bx = blockIdx.x;
    int adj = bx / BLK_PER_ADJ;
    int blk = bx % BLK_PER_ADJ;
    int t = threadIdx.x;
    int i = blk * SCAN_B + t;
    int v = (i < NNODES) ? g_cnt[adj * NNODES + i] : 0;
    s[t] = v;
    __syncthreads();
#pragma unroll
    for (int off = 1; off < SCAN_B; off <<= 1) {
        int u = (t >= off) ? s[t - off] : 0;
        __syncthreads();
        s[t] += u;
        __syncthreads();
    }
    if (i < NNODES) g_cnt[adj * NNODES + i] = s[t] - v;
    if (t == SCAN_B - 1) g_blksum[adj * BLK_PER_ADJ + blk] = s[t];
}

__global__ __launch_bounds__(512) void scanB_kernel() {
    __shared__ int sb[NADJ * BLK_PER_ADJ];
    int t = threadIdx.x;
    for (int i = t; i < NADJ * BLK_PER_ADJ; i += blockDim.x) sb[i] = g_blksum[i];
    __syncthreads();
    if (t < NADJ) {
        int run = 0;
        for (int k = 0; k < BLK_PER_ADJ; k++) {
            int v = sb[t * BLK_PER_ADJ + k];
            sb[t * BLK_PER_ADJ + k] = run;
            run += v;
        }
        g_rowptr[t * (NNODES + 1) + NNODES] = run;
    }
    __syncthreads();
    for (int i = t; i < NADJ * BLK_PER_ADJ; i += blockDim.x) g_blksum[i] = sb[i];
}

__global__ __launch_bounds__(SCAN_B) void scanC_kernel() {
    int bx = blockIdx.x;
    int adj = bx / BLK_PER_ADJ;
    int blk = bx % BLK_PER_ADJ;
    int t = threadIdx.x;
    int i = blk * SCAN_B + t;
    if (i >= NNODES) return;
    int val = g_cnt[adj * NNODES + i] + g_blksum[adj * BLK_PER_ADJ + blk];
    g_rowptr[adj * (NNODES + 1) + i] = val;
    g_cur[adj * NNODES + i] = val;
}

// 4 edges per thread
__global__ void scatter_kernel(const int4* __restrict__ rows4,
                               const int4* __restrict__ cols4,
                               const float4* __restrict__ vals4) {
    int i = blockIdx.x * blockDim.x + threadIdx.x;
    if (i >= NADJ * NEDGE / 4) return;
    int adj = (i * 4) / NEDGE;
    if (!g_used[adj]) return;
    int4 r = __ldg(rows4 + i);
    int4 c = __ldg(cols4 + i);
    float4 v = __ldg(vals4 + i);
    int* cur = g_cur + adj * NNODES;
    int2* ed = (int2*)(g_edge + (size_t)adj * NEDGE);
    int p0 = atomicAdd(cur + r.x, 1);
    ed[p0] = make_int2(c.x, __float_as_int(v.x));
    int p1 = atomicAdd(cur + r.y, 1);
    ed[p1] = make_int2(c.y, __float_as_int(v.y));
    int p2 = atomicAdd(cur + r.z, 1);
    ed[p2] = make_int2(c.z, __float_as_int(v.z));
    int p3 = atomicAdd(cur + r.w, 1);
    ed[p3] = make_int2(c.w, __float_as_int(v.w));
}

// ---------------- TF32 split tensor-core GEMM, fp16 output ----------------
#define GBM 128
#define GBN 128
#define GBK 16
#define SPAD 20

__device__ __forceinline__ float f2tf32(float x) {
    float r;
    asm("cvt.rna.tf32.f32 %0, %1;" : "=f"(r) : "f"(x));
    return r;
}

__device__ __forceinline__ void mma_tf32(float* d, const float* a, float b0, float b1) {
    asm volatile(
        "mma.sync.aligned.m16n8k8.row.col.f32.tf32.tf32.f32 "
        "{%0,%1,%2,%3}, {%4,%5,%6,%7}, {%8,%9}, {%0,%1,%2,%3};"
        : "+f"(d[0]), "+f"(d[1]), "+f"(d[2]), "+f"(d[3])
        : "r"(__float_as_uint(a[0])), "r"(__float_as_uint(a[1])),
          "r"(__float_as_uint(a[2])), "r"(__float_as_uint(a[3])),
          "r"(__float_as_uint(b0)), "r"(__float_as_uint(b1)));
}

__global__ __launch_bounds__(256) void gemm_tf32_kernel(
    const float* __restrict__ A, const float* __restrict__ W,
    const float* __restrict__ bias, __half* __restrict__ C) {
    __shared__ float As_hi[GBM][SPAD];
    __shared__ float As_lo[GBM][SPAD];
    __shared__ float Bs_hi[GBN][SPAD];
    __shared__ float Bs_lo[GBN][SPAD];

    int t = threadIdx.x;
    int m0 = blockIdx.x * GBM;
    int n0 = blockIdx.y * GBN;
    int ws = t >> 5, lane = t & 31;
    int wm = ws & 3, wn = ws >> 2;
    int g = lane >> 2, t4 = lane & 3;

    float acc[2][8][4];
#pragma unroll
    for (int i = 0; i < 2; i++)
#pragma unroll
        for (int j = 0; j < 8; j++)
#pragma unroll
            for (int q = 0; q < 4; q++) acc[i][j][q] = 0.f;

    for (int k0 = 0; k0 < NH; k0 += GBK) {
#pragma unroll
        for (int L = 0; L < 2; L++) {
            int f = t + L * 256;
            int m = f >> 2, c4 = f & 3;
            int gm = m0 + m;
            float4 v = make_float4(0.f, 0.f, 0.f, 0.f);
            if (gm < NNODES)
                v = *(const float4*)(A + (size_t)gm * NH + k0 + c4 * 4);
            float4 h, l;
            h.x = f2tf32(v.x); l.x = f2tf32(v.x - h.x);
            h.y = f2tf32(v.y); l.y = f2tf32(v.y - h.y);
            h.z = f2tf32(v.z); l.z = f2tf32(v.z - h.z);
            h.w = f2tf32(v.w); l.w = f2tf32(v.w - h.w);
            *(float4*)&As_hi[m][c4 * 4] = h;
            *(float4*)&As_lo[m][c4 * 4] = l;
        }
#pragma unroll
        for (int L = 0; L < 2; L++) {
            int f = t + L * 256;
            int n = f >> 2, c4 = f & 3;
            float4 v = *(const float4*)(W + (size_t)(n0 + n) * NH + k0 + c4 * 4);
            float4 h, l;
            h.x = f2tf32(v.x); l.x = f2tf32(v.x - h.x);
            h.y = f2tf32(v.y); l.y = f2tf32(v.y - h.y);
            h.z = f2tf32(v.z); l.z = f2tf32(v.z - h.z);
            h.w = f2tf32(v.w); l.w = f2tf32(v.w - h.w);
            *(float4*)&Bs_hi[n][c4 * 4] = h;
            *(float4*)&Bs_lo[n][c4 * 4] = l;
        }
        __syncthreads();

#pragma unroll
        for (int k8 = 0; k8 < GBK / 8; k8++) {
            int kb = k8 * 8;
            float ah[2][4], al[2][4];
#pragma unroll
            for (int i = 0; i < 2; i++) {
                int mr = wm * 32 + i * 16;
                ah[i][0] = As_hi[mr + g][kb + t4];
                ah[i][1] = As_hi[mr + g + 8][kb + t4];
                ah[i][2] = As_hi[mr + g][kb + t4 + 4];
                ah[i][3] = As_hi[mr + g + 8][kb + t4 + 4];
                al[i][0] = As_lo[mr + g][kb + t4];
                al[i][1] = As_lo[mr + g + 8][kb + t4];
                al[i][2] = As_lo[mr + g][kb + t4 + 4];
                al[i][3] = As_lo[mr + g + 8][kb + t4 + 4];
            }
#pragma unroll
            for (int j = 0; j < 8; j++) {
                int nb = wn * 64 + j * 8;
                float b0h = Bs_hi[nb + g][kb + t4];
                float b1h = Bs_hi[nb + g][kb + t4 + 4];
                float b0l = Bs_lo[nb + g][kb + t4];
                float b1l = Bs_lo[nb + g][kb + t4 + 4];
#pragma unroll
                for (int i = 0; i < 2; i++) {
                    mma_tf32(acc[i][j], ah[i], b0h, b1h);
                    mma_tf32(acc[i][j], ah[i], b0l, b1l);
                    mma_tf32(acc[i][j], al[i], b0h, b1h);
                }
            }
        }
        __syncthreads();
    }

#pragma unroll
    for (int j = 0; j < 8; j++) {
        int c = n0 + wn * 64 + j * 8 + 2 * t4;
        float bx = __ldg(bias + c);
        float by = __ldg(bias + c + 1);
#pragma unroll
        for (int i = 0; i < 2; i++) {
            int r0 = m0 + wm * 32 + i * 16 + g;
            if (r0 < NNODES) {
                *(half2*)(C + (size_t)r0 * NH + c) =
                    __floats2half2_rn(acc[i][j][0] + bx, acc[i][j][1] + by);
            }
            int r1 = r0 + 8;
            if (r1 < NNODES) {
                *(half2*)(C + (size_t)r1 * NH + c) =
                    __floats2half2_rn(acc[i][j][2] + bx, acc[i][j][3] + by);
            }
        }
    }
}

// ---------------- CSR SpMM primitives -------------------------------------
// Each lane owns 8 consecutive cols (lane*8 .. lane*8+7) = one uint4 of halves.
__device__ __forceinline__ void gather_accum(float* acc, const __half* __restrict__ src,
                                             int c, float v, int lane) {
    const uint4* row = (const uint4*)(src + (size_t)c * NH);
    uint4 pv = __ldg(row + lane);
    const __half2* h = (const __half2*)&pv;
    float2 f0 = __half22float2(h[0]);
    float2 f1 = __half22float2(h[1]);
    float2 f2 = __half22float2(h[2]);
    float2 f3 = __half22float2(h[3]);
    acc[0] += v * f0.x; acc[1] += v * f0.y;
    acc[2] += v * f1.x; acc[3] += v * f1.y;
    acc[4] += v * f2.x; acc[5] += v * f2.y;
    acc[6] += v * f3.x; acc[7] += v * f3.y;
}

__device__ __forceinline__ void spmm_row(float* acc, int w, int lane,
                                         const __half* __restrict__ src, int selpos) {
    int adj = g_adj_idx[selpos];
    const int* rp = g_rowptr + adj * (NNODES + 1);
    int beg = __ldg(rp + w), end = __ldg(rp + w + 1);
    const int2* ed = g_edge + (size_t)adj * NEDGE;
    int2 e0 = make_int2(0, 0);
    if (beg < end) e0 = __ldcs(ed + beg);   // streaming: don't displace gather rows
    for (int e = beg; e < end; e++) {
        int2 en = make_int2(0, 0);
        if (e + 1 < end) en = __ldcs(ed + e + 1);
        gather_accum(acc, src, e0.x, __int_as_float(e0.y), lane);
        e0 = en;
    }
}

__device__ __forceinline__ void store_row_h(float* acc, __half* __restrict__ dst,
                                            int w, int lane) {
    uint4 pk;
    half2* ph = (half2*)&pk;
    ph[0] = __floats2half2_rn(acc[0], acc[1]);
    ph[1] = __floats2half2_rn(acc[2], acc[3]);
    ph[2] = __floats2half2_rn(acc[4], acc[5]);
    ph[3] = __floats2half2_rn(acc[6], acc[7]);
    ((uint4*)(dst + (size_t)w * NH))[lane] = pk;
}

// dst = adjA@srcA                          (NSRC==1)
// dst = adjA@srcA + adjB@srcB              (NSRC==2)
template <int NSRC>
__global__ __launch_bounds__(256) void spmm_kernel(
    const __half* __restrict__ srcA, int selA,
    const __half* __restrict__ srcB, int selB,
    __half* __restrict__ dst) {
    int w = (blockIdx.x * blockDim.x + threadIdx.x) >> 5;
    int lane = threadIdx.x & 31;
    if (w >= NNODES) return;
    float acc[8];
#pragma unroll
    for (int i = 0; i < 8; i++) acc[i] = 0.f;
    spmm_row(acc, w, lane, srcA, selA);
    if (NSRC >= 2) spmm_row(acc, w, lane, srcB, selB);
    store_row_h(acc, dst, w, lane);
}

// out = GELU(LN(adjA@srcA + adjB@srcB + adjC@srcC))
__global__ __launch_bounds__(256) void spmm3_ln_gelu_kernel(
    const __half* __restrict__ srcA, int selA,
    const __half* __restrict__ srcB, int selB,
    const __half* __restrict__ srcC, int selC,
    const float* __restrict__ gamma, const float* __restrict__ beta,
    float* __restrict__ out) {
    int w = (blockIdx.x * blockDim.x + threadIdx.x) >> 5;
    int lane = threadIdx.x & 31;
    if (w >= NNODES) return;
    float acc[8];
#pragma unroll
    for (int i = 0; i < 8; i++) acc[i] = 0.f;
    spmm_row(acc, w, lane, srcA, selA);
    spmm_row(acc, w, lane, srcB, selB);
    spmm_row(acc, w, lane, srcC, selC);

    float sum = 0.f, sq = 0.f;
#pragma unroll
    for (int i = 0; i < 8; i++) { sum += acc[i]; sq += acc[i] * acc[i]; }
#pragma unroll
    for (int off = 16; off >= 1; off >>= 1) {
        sum += __shfl_xor_sync(0xFFFFFFFFu, sum, off);
        sq  += __shfl_xor_sync(0xFFFFFFFFu, sq, off);
    }
    float mean = sum * (1.f / NH);
    float var = sq * (1.f / NH) - mean * mean;
    float inv = rsqrtf(var + LN_EPS);

    const float4* g4 = (const float4*)gamma;
    const float4* b4 = (const float4*)beta;
    float4 ga = __ldg(g4 + lane * 2), gb = __ldg(g4 + lane * 2 + 1);
    float4 ba = __ldg(b4 + lane * 2), bb = __ldg(b4 + lane * 2 + 1);
    float gs[8] = {ga.x, ga.y, ga.z, ga.w, gb.x, gb.y, gb.z, gb.w};
    float bs[8] = {ba.x, ba.y, ba.z, ba.w, bb.x, bb.y, bb.z, bb.w};
    float r[8];
#pragma unroll
    for (int i = 0; i < 8; i++) {
        float y = (acc[i] - mean) * inv * gs[i] + bs[i];
        r[i] = 0.5f * y * (1.f + erff(y * 0.70710678118654752f));
    }
    float4* o4 = (float4*)(out + (size_t)w * NH);
    o4[lane * 2] = make_float4(r[0], r[1], r[2], r[3]);
    o4[lane * 2 + 1] = make_float4(r[4], r[5], r[6], r[7]);
}

// ---------------- launch ---------------------------------------------
extern "C" void kernel_launch(void* const* d_in, const int* in_sizes, int n_in,
                              void* d_out, int out_size) {
    const float* x    = (const float*)d_in[0];
    const int* rows   = (const int*)d_in[1];
    const int* cols   = (const int*)d_in[2];
    const float* vals = (const float*)d_in[3];
    const int* seqr   = (const int*)d_in[4];
    const int* resr   = (const int*)d_in[5];
    const float* W    = (const float*)d_in[6];
    const float* b    = (const float*)d_in[7];
    const float* gamma = (const float*)d_in[8];
    const float* beta  = (const float*)d_in[9];
    float* out = (float*)d_out;

    static __half *s0p = nullptr, *s1p, *s2p;
    static cudaStream_t st2;
    static cudaEvent_t evFork, evGemm;
    if (!s0p) {
        cudaGetSymbolAddress((void**)&s0p, g_state0);
        cudaGetSymbolAddress((void**)&s1p, g_state1);
        cudaGetSymbolAddress((void**)&s2p, g_state2);
        cudaStreamCreateWithFlags(&st2, cudaStreamNonBlocking);
        cudaEventCreateWithFlags(&evFork, cudaEventDisableTiming);
        cudaEventCreateWithFlags(&evGemm, cudaEventDisableTiming);
    }

    const int spmm_blocks = (NNODES + 7) / 8;  // warp per row, 8 warps/block
    const int e4_blocks = (NADJ * NEDGE / 4 + 255) / 256;

    // fork: GEMM on st2 runs concurrently with the CSR build chain
    cudaEventRecord(evFork, 0);
    cudaStreamWaitEvent(st2, evFork, 0);
    gemm_tf32_kernel<<<dim3((NNODES + GBM - 1) / GBM, NH / GBN), 256, 0, st2>>>(x, W, b, s0p);
    cudaEventRecord(evGemm, st2);

    // CSR build on the main (captured) stream
    decode_idx_kernel<<<1, 1>>>(seqr, resr);
    zero_cnt_kernel<<<(NADJ * NNODES + 255) / 256, 256>>>();
    hist_kernel<<<e4_blocks, 256>>>((const int4*)rows);
    scanA_kernel<<<NADJ * BLK_PER_ADJ, SCAN_B>>>();
    scanB_kernel<<<1, 512>>>();
    scanC_kernel<<<NADJ * BLK_PER_ADJ, SCAN_B>>>();
    scatter_kernel<<<e4_blocks, 256>>>((const int4*)rows, (const int4*)cols,
                                       (const float4*)vals);

    // join: chain needs both GEMM output and CSR
    cudaStreamWaitEvent(0, evGemm, 0);

    // s1 = seq0@s0
    spmm_kernel<1><<<spmm_blocks, 256>>>(s0p, 0, nullptr, 0, s1p);
    // s2 = seq1@s1 + res0@s0
    spmm_kernel<2><<<spmm_blocks, 256>>>(s1p, 1, s0p, 3, s2p);
    // out = GELU(LN(seq2@s2 + res1@s0 + res2@s1))
    spmm3_ln_gelu_kernel<<<spmm_blocks, 256>>>(s2p, 2, s0p, 4, s1p, 5, gamma, beta, out);
}

// round 16
// speedup vs baseline: 1.0727x; 1.0727x over previous
#include <cuda_runtime.h>
#include <cuda_fp16.h>
#include <math.h>

#define NNODES 50000
#define NADJ   6
#define NEDGE  800000
#define NH     256
#define LN_EPS 1e-5f

#define SCAN_B 1024
#define BLK_PER_ADJ ((NNODES + SCAN_B - 1) / SCAN_B)   // 49

// ---------------- device scratch (no allocations allowed) ----------------
static __device__ __align__(16) __half g_state0[(size_t)NNODES * NH];
static __device__ __align__(16) __half g_state1[(size_t)NNODES * NH];
static __device__ __align__(16) __half g_state2[(size_t)NNODES * NH];
static __device__ int   g_cnt[NADJ * NNODES];
static __device__ int   g_rowptr[NADJ * (NNODES + 1)];
static __device__ int   g_cur[NADJ * NNODES];
static __device__ int   g_blksum[NADJ * BLK_PER_ADJ];
static __device__ __align__(16) int2 g_edge[(size_t)NADJ * NEDGE];  // {col, val bits}
static __device__ int   g_adj_idx[6];   // [seq0,seq1,seq2,res0,res1,res2]
static __device__ int   g_used[NADJ];

// ---------------- idx decode: int32 vs int64 autodetect -------------------
__global__ void decode_idx_kernel(const int* __restrict__ seq_raw,
                                  const int* __restrict__ res_raw) {
    if (threadIdx.x != 0 || blockIdx.x != 0) return;
    long long a[6];
    int b[6];
    bool v64 = true, v32 = true;
    const long long* s64 = (const long long*)seq_raw;
    const long long* r64 = (const long long*)res_raw;
#pragma unroll
    for (int i = 0; i < 3; i++) {
        long long t = s64[i]; a[i] = t;     if (t < 0 || t >= NADJ) v64 = false;
        long long u = r64[i]; a[3 + i] = u; if (u < 0 || u >= NADJ) v64 = false;
        int p = seq_raw[i]; b[i] = p;       if (p < 0 || p >= NADJ) v32 = false;
        int q = res_raw[i]; b[3 + i] = q;   if (q < 0 || q >= NADJ) v32 = false;
    }
    (void)v32;
#pragma unroll
    for (int i = 0; i < NADJ; i++) g_used[i] = 0;
#pragma unroll
    for (int i = 0; i < 6; i++) {
        int v = v64 ? (int)a[i] : b[i];
        g_adj_idx[i] = v;
        g_used[v] = 1;
    }
}

// ---------------- CSR build --------------------------------------------
__global__ void zero_cnt_kernel() {
    int i = blockIdx.x * blockDim.x + threadIdx.x;
    if (i < NADJ * NNODES) g_cnt[i] = 0;
}

// 4 edges per thread (NEDGE % 4 == 0, so all 4 share an adjacency)
__global__ void hist_kernel(const int4* __restrict__ rows4) {
    int i = blockIdx.x * blockDim.x + threadIdx.x;
    if (i >= NADJ * NEDGE / 4) return;
    int adj = (i * 4) / NEDGE;
    if (!g_used[adj]) return;
    int4 r = __ldg(rows4 + i);
    int* cnt = g_cnt + adj * NNODES;
    atomicAdd(cnt + r.x, 1);
    atomicAdd(cnt + r.y, 1);
    atomicAdd(cnt + r.z, 1);
    atomicAdd(cnt + r.w, 1);
}

__global__ __launch_bounds__(SCAN_B) void scanA_kernel() {
    __shared__ int s[SCAN_B];
    int bx = blockIdx.x;
    int adj = bx / BLK_PER_ADJ;
    int blk = bx % BLK_PER_ADJ;
    int t = threadIdx.x;
    int i = blk * SCAN_B + t;
    int v = (i < NNODES) ? g_cnt[adj * NNODES + i] : 0;
    s[t] = v;
    __syncthreads();
#pragma unroll
    for (int off = 1; off < SCAN_B; off <<= 1) {
        int u = (t >= off) ? s[t - off] : 0;
        __syncthreads();
        s[t] += u;
        __syncthreads();
    }
    if (i < NNODES) g_cnt[adj * NNODES + i] = s[t] - v;
    if (t == SCAN_B - 1) g_blksum[adj * BLK_PER_ADJ + blk] = s[t];
}

__global__ __launch_bounds__(512) void scanB_kernel() {
    __shared__ int sb[NADJ * BLK_PER_ADJ];
    int t = threadIdx.x;
    for (int i = t; i < NADJ * BLK_PER_ADJ; i += blockDim.x) sb[i] = g_blksum[i];
    __syncthreads();
    if (t < NADJ) {
        int run = 0;
        for (int k = 0; k < BLK_PER_ADJ; k++) {
            int v = sb[t * BLK_PER_ADJ + k];
            sb[t * BLK_PER_ADJ + k] = run;
            run += v;
        }
        g_rowptr[t * (NNODES + 1) + NNODES] = run;
    }
    __syncthreads();
    for (int i = t; i < NADJ * BLK_PER_ADJ; i += blockDim.x) g_blksum[i] = sb[i];
}

__global__ __launch_bounds__(SCAN_B) void scanC_kernel() {
    int bx = blockIdx.x;
    int adj = bx / BLK_PER_ADJ;
    int blk = bx % BLK_PER_ADJ;
    int t = threadIdx.x;
    int i = blk * SCAN_B + t;
    if (i >= NNODES) return;
    int val = g_cnt[adj * NNODES + i] + g_blksum[adj * BLK_PER_ADJ + blk];
    g_rowptr[adj * (NNODES + 1) + i] = val;
    g_cur[adj * NNODES + i] = val;
}

// 4 edges per thread
__global__ void scatter_kernel(const int4* __restrict__ rows4,
                               const int4* __restrict__ cols4,
                               const float4* __restrict__ vals4) {
    int i = blockIdx.x * blockDim.x + threadIdx.x;
    if (i >= NADJ * NEDGE / 4) return;
    int adj = (i * 4) / NEDGE;
    if (!g_used[adj]) return;
    int4 r = __ldg(rows4 + i);
    int4 c = __ldg(cols4 + i);
    float4 v = __ldg(vals4 + i);
    int* cur = g_cur + adj * NNODES;
    int2* ed = (int2*)(g_edge + (size_t)adj * NEDGE);
    int p0 = atomicAdd(cur + r.x, 1);
    ed[p0] = make_int2(c.x, __float_as_int(v.x));
    int p1 = atomicAdd(cur + r.y, 1);
    ed[p1] = make_int2(c.y, __float_as_int(v.y));
    int p2 = atomicAdd(cur + r.z, 1);
    ed[p2] = make_int2(c.z, __float_as_int(v.z));
    int p3 = atomicAdd(cur + r.w, 1);
    ed[p3] = make_int2(c.w, __float_as_int(v.w));
}

// ---------------- TF32 split tensor-core GEMM, fp16 output ----------------
#define GBM 128
#define GBN 128
#define GBK 16
#define SPAD 20

__device__ __forceinline__ float f2tf32(float x) {
    float r;
    asm("cvt.rna.tf32.f32 %0, %1;" : "=f"(r) : "f"(x));
    return r;
}

__device__ __forceinline__ void mma_tf32(float* d, const float* a, float b0, float b1) {
    asm volatile(
        "mma.sync.aligned.m16n8k8.row.col.f32.tf32.tf32.f32 "
        "{%0,%1,%2,%3}, {%4,%5,%6,%7}, {%8,%9}, {%0,%1,%2,%3};"
        : "+f"(d[0]), "+f"(d[1]), "+f"(d[2]), "+f"(d[3])
        : "r"(__float_as_uint(a[0])), "r"(__float_as_uint(a[1])),
          "r"(__float_as_uint(a[2])), "r"(__float_as_uint(a[3])),
          "r"(__float_as_uint(b0)), "r"(__float_as_uint(b1)));
}

__global__ __launch_bounds__(256) void gemm_tf32_kernel(
    const float* __restrict__ A, const float* __restrict__ W,
    const float* __restrict__ bias, __half* __restrict__ C) {
    __shared__ float As_hi[GBM][SPAD];
    __shared__ float As_lo[GBM][SPAD];
    __shared__ float Bs_hi[GBN][SPAD];
    __shared__ float Bs_lo[GBN][SPAD];

    int t = threadIdx.x;
    int m0 = blockIdx.x * GBM;
    int n0 = blockIdx.y * GBN;
    int ws = t >> 5, lane = t & 31;
    int wm = ws & 3, wn = ws >> 2;
    int g = lane >> 2, t4 = lane & 3;

    float acc[2][8][4];
#pragma unroll
    for (int i = 0; i < 2; i++)
#pragma unroll
        for (int j = 0; j < 8; j++)
#pragma unroll
            for (int q = 0; q < 4; q++) acc[i][j][q] = 0.f;

    for (int k0 = 0; k0 < NH; k0 += GBK) {
#pragma unroll
        for (int L = 0; L < 2; L++) {
            int f = t + L * 256;
            int m = f >> 2, c4 = f & 3;
            int gm = m0 + m;
            float4 v = make_float4(0.f, 0.f, 0.f, 0.f);
            if (gm < NNODES)
                v = *(const float4*)(A + (size_t)gm * NH + k0 + c4 * 4);
            float4 h, l;
            h.x = f2tf32(v.x); l.x = f2tf32(v.x - h.x);
            h.y = f2tf32(v.y); l.y = f2tf32(v.y - h.y);
            h.z = f2tf32(v.z); l.z = f2tf32(v.z - h.z);
            h.w = f2tf32(v.w); l.w = f2tf32(v.w - h.w);
            *(float4*)&As_hi[m][c4 * 4] = h;
            *(float4*)&As_lo[m][c4 * 4] = l;
        }
#pragma unroll
        for (int L = 0; L < 2; L++) {
            int f = t + L * 256;
            int n = f >> 2, c4 = f & 3;
            float4 v = *(const float4*)(W + (size_t)(n0 + n) * NH + k0 + c4 * 4);
            float4 h, l;
            h.x = f2tf32(v.x); l.x = f2tf32(v.x - h.x);
            h.y = f2tf32(v.y); l.y = f2tf32(v.y - h.y);
            h.z = f2tf32(v.z); l.z = f2tf32(v.z - h.z);
            h.w = f2tf32(v.w); l.w = f2tf32(v.w - h.w);
            *(float4*)&Bs_hi[n][c4 * 4] = h;
            *(float4*)&Bs_lo[n][c4 * 4] = l;
        }
        __syncthreads();

#pragma unroll
        for (int k8 = 0; k8 < GBK / 8; k8++) {
            int kb = k8 * 8;
            float ah[2][4], al[2][4];
#pragma unroll
            for (int i = 0; i < 2; i++) {
                int mr = wm * 32 + i * 16;
                ah[i][0] = As_hi[mr + g][kb + t4];
                ah[i][1] = As_hi[mr + g + 8][kb + t4];
                ah[i][2] = As_hi[mr + g][kb + t4 + 4];
                ah[i][3] = As_hi[mr + g + 8][kb + t4 + 4];
                al[i][0] = As_lo[mr + g][kb + t4];
                al[i][1] = As_lo[mr + g + 8][kb + t4];
                al[i][2] = As_lo[mr + g][kb + t4 + 4];
                al[i][3] = As_lo[mr + g + 8][kb + t4 + 4];
            }
#pragma unroll
            for (int j = 0; j < 8; j++) {
                int nb = wn * 64 + j * 8;
                float b0h = Bs_hi[nb + g][kb + t4];
                float b1h = Bs_hi[nb + g][kb + t4 + 4];
                float b0l = Bs_lo[nb + g][kb + t4];
                float b1l = Bs_lo[nb + g][kb + t4 + 4];
#pragma unroll
                for (int i = 0; i < 2; i++) {
                    mma_tf32(acc[i][j], ah[i], b0h, b1h);
                    mma_tf32(acc[i][j], ah[i], b0l, b1l);
                    mma_tf32(acc[i][j], al[i], b0h, b1h);
                }
            }
        }
        __syncthreads();
    }

#pragma unroll
    for (int j = 0; j < 8; j++) {
        int c = n0 + wn * 64 + j * 8 + 2 * t4;
        float bx = __ldg(bias + c);
        float by = __ldg(bias + c + 1);
#pragma unroll
        for (int i = 0; i < 2; i++) {
            int r0 = m0 + wm * 32 + i * 16 + g;
            if (r0 < NNODES) {
                *(half2*)(C + (size_t)r0 * NH + c) =
                    __floats2half2_rn(acc[i][j][0] + bx, acc[i][j][1] + by);
            }
            int r1 = r0 + 8;
            if (r1 < NNODES) {
                *(half2*)(C + (size_t)r1 * NH + c) =
                    __floats2half2_rn(acc[i][j][2] + bx, acc[i][j][3] + by);
            }
        }
    }
}

// ---------------- CSR SpMM primitives -------------------------------------
// Each lane owns 8 consecutive cols (lane*8 .. lane*8+7) = one uint4 of halves.
__device__ __forceinline__ void accum8(float* acc, uint4 pv, float v) {
    const __half2* h = (const __half2*)&pv;
    float2 f0 = __half22float2(h[0]);
    float2 f1 = __half22float2(h[1]);
    float2 f2 = __half22float2(h[2]);
    float2 f3 = __half22float2(h[3]);
    acc[0] += v * f0.x; acc[1] += v * f0.y;
    acc[2] += v * f1.x; acc[3] += v * f1.y;
    acc[4] += v * f2.x; acc[5] += v * f2.y;
    acc[6] += v * f3.x; acc[7] += v * f3.y;
}

// 4-edge unrolled gather: 4 independent 512B row reads in flight per iteration
__device__ __forceinline__ void spmm_row(float* acc, int w, int lane,
                                         const __half* __restrict__ src, int selpos) {
    int adj = g_adj_idx[selpos];
    const int* rp = g_rowptr + adj * (NNODES + 1);
    int beg = __ldg(rp + w), end = __ldg(rp + w + 1);
    const int2* ed = g_edge + (size_t)adj * NEDGE;
    int e = beg;
    // prologue: align e to even index so int4 edge loads are 16B-aligned
    if ((e & 1) && e < end) {
        int2 ev = __ldg(ed + e);
        uint4 pv = __ldg((const uint4*)(src + (size_t)ev.x * NH) + lane);
        accum8(acc, pv, __int_as_float(ev.y));
        e++;
    }
    for (; e + 4 <= end; e += 4) {
        int4 ea = __ldg((const int4*)(ed + e));       // edges e, e+1
        int4 eb = __ldg((const int4*)(ed + e) + 1);   // edges e+2, e+3
        uint4 v0 = __ldg((const uint4*)(src + (size_t)ea.x * NH) + lane);
        uint4 v1 = __ldg((const uint4*)(src + (size_t)ea.z * NH) + lane);
        uint4 v2 = __ldg((const uint4*)(src + (size_t)eb.x * NH) + lane);
        uint4 v3 = __ldg((const uint4*)(src + (size_t)eb.z * NH) + lane);
        accum8(acc, v0, __int_as_float(ea.y));
        accum8(acc, v1, __int_as_float(ea.w));
        accum8(acc, v2, __int_as_float(eb.y));
        accum8(acc, v3, __int_as_float(eb.w));
    }
    for (; e < end; e++) {
        int2 ev = __ldg(ed + e);
        uint4 pv = __ldg((const uint4*)(src + (size_t)ev.x * NH) + lane);
        accum8(acc, pv, __int_as_float(ev.y));
    }
}

__device__ __forceinline__ void store_row_h(float* acc, __half* __restrict__ dst,
                                            int w, int lane) {
    uint4 pk;
    half2* ph = (half2*)&pk;
    ph[0] = __floats2half2_rn(acc[0], acc[1]);
    ph[1] = __floats2half2_rn(acc[2], acc[3]);
    ph[2] = __floats2half2_rn(acc[4], acc[5]);
    ph[3] = __floats2half2_rn(acc[6], acc[7]);
    ((uint4*)(dst + (size_t)w * NH))[lane] = pk;
}

// dst = adjA@srcA                          (NSRC==1)
// dst = adjA@srcA + adjB@srcB              (NSRC==2)
template <int NSRC>
__global__ __launch_bounds__(256) void spmm_kernel(
    const __half* __restrict__ srcA, int selA,
    const __half* __restrict__ srcB, int selB,
    __half* __restrict__ dst) {
    int w = (blockIdx.x * blockDim.x + threadIdx.x) >> 5;
    int lane = threadIdx.x & 31;
    if (w >= NNODES) return;
    float acc[8];
#pragma unroll
    for (int i = 0; i < 8; i++) acc[i] = 0.f;
    spmm_row(acc, w, lane, srcA, selA);
    if (NSRC >= 2) spmm_row(acc, w, lane, srcB, selB);
    store_row_h(acc, dst, w, lane);
}

// out = GELU(LN(adjA@srcA + adjB@srcB + adjC@srcC))
__global__ __launch_bounds__(256) void spmm3_ln_gelu_kernel(
    const __half* __restrict__ srcA, int selA,
    const __half* __restrict__ srcB, int selB,
    const __half* __restrict__ srcC, int selC,
    const float* __restrict__ gamma, const float* __restrict__ beta,
    float* __restrict__ out) {
    int w = (blockIdx.x * blockDim.x + threadIdx.x) >> 5;
    int lane = threadIdx.x & 31;
    if (w >= NNODES) return;
    float acc[8];
#pragma unroll
    for (int i = 0; i < 8; i++) acc[i] = 0.f;
    spmm_row(acc, w, lane, srcA, selA);
    spmm_row(acc, w, lane, srcB, selB);
    spmm_row(acc, w, lane, srcC, selC);

    float sum = 0.f, sq = 0.f;
#pragma unroll
    for (int i = 0; i < 8; i++) { sum += acc[i]; sq += acc[i] * acc[i]; }
#pragma unroll
    for (int off = 16; off >= 1; off >>= 1) {
        sum += __shfl_xor_sync(0xFFFFFFFFu, sum, off);
        sq  += __shfl_xor_sync(0xFFFFFFFFu, sq, off);
    }
    float mean = sum * (1.f / NH);
    float var = sq * (1.f / NH) - mean * mean;
    float inv = rsqrtf(var + LN_EPS);

    const float4* g4 = (const float4*)gamma;
    const float4* b4 = (const float4*)beta;
    float4 ga = __ldg(g4 + lane * 2), gb = __ldg(g4 + lane * 2 + 1);
    float4 ba = __ldg(b4 + lane * 2), bb = __ldg(b4 + lane * 2 + 1);
    float gs[8] = {ga.x, ga.y, ga.z, ga.w, gb.x, gb.y, gb.z, gb.w};
    float bs[8] = {ba.x, ba.y, ba.z, ba.w, bb.x, bb.y, bb.z, bb.w};
    float r[8];
#pragma unroll
    for (int i = 0; i < 8; i++) {
        float y = (acc[i] - mean) * inv * gs[i] + bs[i];
        r[i] = 0.5f * y * (1.f + erff(y * 0.70710678118654752f));
    }
    float4* o4 = (float4*)(out + (size_t)w * NH);
    o4[lane * 2] = make_float4(r[0], r[1], r[2], r[3]);
    o4[lane * 2 + 1] = make_float4(r[4], r[5], r[6], r[7]);
}

// ---------------- launch ---------------------------------------------
extern "C" void kernel_launch(void* const* d_in, const int* in_sizes, int n_in,
                              void* d_out, int out_size) {
    const float* x    = (const float*)d_in[0];
    const int* rows   = (const int*)d_in[1];
    const int* cols   = (const int*)d_in[2];
    const float* vals = (const float*)d_in[3];
    const int* seqr   = (const int*)d_in[4];
    const int* resr   = (const int*)d_in[5];
    const float* W    = (const float*)d_in[6];
    const float* b    = (const float*)d_in[7];
    const float* gamma = (const float*)d_in[8];
    const float* beta  = (const float*)d_in[9];
    float* out = (float*)d_out;

    static __half *s0p = nullptr, *s1p, *s2p;
    static cudaStream_t st2;
    static cudaEvent_t evFork, evGemm;
    if (!s0p) {
        cudaGetSymbolAddress((void**)&s0p, g_state0);
        cudaGetSymbolAddress((void**)&s1p, g_state1);
        cudaGetSymbolAddress((void**)&s2p, g_state2);
        cudaStreamCreateWithFlags(&st2, cudaStreamNonBlocking);
        cudaEventCreateWithFlags(&evFork, cudaEventDisableTiming);
        cudaEventCreateWithFlags(&evGemm, cudaEventDisableTiming);
    }

    const int spmm_blocks = (NNODES + 7) / 8;  // warp per row, 8 warps/block
    const int e4_blocks = (NADJ * NEDGE / 4 + 255) / 256;

    // fork: GEMM on st2 runs concurrently with the CSR build chain
    cudaEventRecord(evFork, 0);
    cudaStreamWaitEvent(st2, evFork, 0);
    gemm_tf32_kernel<<<dim3((NNODES + GBM - 1) / GBM, NH / GBN), 256, 0, st2>>>(x, W, b, s0p);
    cudaEventRecord(evGemm, st2);

    // CSR build on the main (captured) stream
    decode_idx_kernel<<<1, 1>>>(seqr, resr);
    zero_cnt_kernel<<<(NADJ * NNODES + 255) / 256, 256>>>();
    hist_kernel<<<e4_blocks, 256>>>((const int4*)rows);
    scanA_kernel<<<NADJ * BLK_PER_ADJ, SCAN_B>>>();
    scanB_kernel<<<1, 512>>>();
    scanC_kernel<<<NADJ * BLK_PER_ADJ, SCAN_B>>>();
    scatter_kernel<<<e4_blocks, 256>>>((const int4*)rows, (const int4*)cols,
                                       (const float4*)vals);

    // join: chain needs both GEMM output and CSR
    cudaStreamWaitEvent(0, evGemm, 0);

    // s1 = seq0@s0
    spmm_kernel<1><<<spmm_blocks, 256>>>(s0p, 0, nullptr, 0, s1p);
    // s2 = seq1@s1 + res0@s0
    spmm_kernel<2><<<spmm_blocks, 256>>>(s1p, 1, s0p, 3, s2p);
    // out = GELU(LN(seq2@s2 + res1@s0 + res2@s1))
    spmm3_ln_gelu_kernel<<<spmm_blocks, 256>>>(s2p, 2, s0p, 4, s1p, 5, gamma, beta, out);
}

// round 17
// speedup vs baseline: 1.1105x; 1.0352x over previous
#include <cuda_runtime.h>
#include <cuda_fp16.h>
#include <cuda_bf16.h>
#include <math.h>

#define NNODES 50000
#define NADJ   6
#define NEDGE  800000
#define NH     256
#define LN_EPS 1e-5f

#define SCAN_B 1024
#define BLK_PER_ADJ ((NNODES + SCAN_B - 1) / SCAN_B)   // 49

// ---------------- device scratch (no allocations allowed) ----------------
static __device__ __align__(16) __half g_state0[(size_t)NNODES * NH];
static __device__ __align__(16) __half g_state1[(size_t)NNODES * NH];
static __device__ __align__(16) __half g_state2[(size_t)NNODES * NH];
static __device__ int   g_cnt[NADJ * NNODES];
static __device__ int   g_rowptr[NADJ * (NNODES + 1)];
static __device__ int   g_cur[NADJ * NNODES];
static __device__ int   g_blksum[NADJ * BLK_PER_ADJ];
static __device__ __align__(16) int2 g_edge[(size_t)NADJ * NEDGE];  // {col, val bits}
static __device__ int   g_adj_idx[6];   // [seq0,seq1,seq2,res0,res1,res2]
static __device__ int   g_used[NADJ];

// ---------------- idx decode: int32 vs int64 autodetect -------------------
__global__ void decode_idx_kernel(const int* __restrict__ seq_raw,
                                  const int* __restrict__ res_raw) {
    if (threadIdx.x != 0 || blockIdx.x != 0) return;
    long long a[6];
    int b[6];
    bool v64 = true, v32 = true;
    const long long* s64 = (const long long*)seq_raw;
    const long long* r64 = (const long long*)res_raw;
#pragma unroll
    for (int i = 0; i < 3; i++) {
        long long t = s64[i]; a[i] = t;     if (t < 0 || t >= NADJ) v64 = false;
        long long u = r64[i]; a[3 + i] = u; if (u < 0 || u >= NADJ) v64 = false;
        int p = seq_raw[i]; b[i] = p;       if (p < 0 || p >= NADJ) v32 = false;
        int q = res_raw[i]; b[3 + i] = q;   if (q < 0 || q >= NADJ) v32 = false;
    }
    (void)v32;
#pragma unroll
    for (int i = 0; i < NADJ; i++) g_used[i] = 0;
#pragma unroll
    for (int i = 0; i < 6; i++) {
        int v = v64 ? (int)a[i] : b[i];
        g_adj_idx[i] = v;
        g_used[v] = 1;
    }
}

// ---------------- CSR build --------------------------------------------
__global__ void zero_cnt_kernel() {
    int i = blockIdx.x * blockDim.x + threadIdx.x;
    if (i < NADJ * NNODES) g_cnt[i] = 0;
}

// 4 edges per thread (NEDGE % 4 == 0, so all 4 share an adjacency)
__global__ void hist_kernel(const int4* __restrict__ rows4) {
    int i = blockIdx.x * blockDim.x + threadIdx.x;
    if (i >= NADJ * NEDGE / 4) return;
    int adj = (i * 4) / NEDGE;
    if (!g_used[adj]) return;
    int4 r = __ldg(rows4 + i);
    int* cnt = g_cnt + adj * NNODES;
    atomicAdd(cnt + r.x, 1);
    atomicAdd(cnt + r.y, 1);
    atomicAdd(cnt + r.z, 1);
    atomicAdd(cnt + r.w, 1);
}

__global__ __launch_bounds__(SCAN_B) void scanA_kernel() {
    __shared__ int s[SCAN_B];
    int bx = blockIdx.x;
    int adj = bx / BLK_PER_ADJ;
    int blk = bx % BLK_PER_ADJ;
    int t = threadIdx.x;
    int i = blk * SCAN_B + t;
    int v = (i < NNODES) ? g_cnt[adj * NNODES + i] : 0;
    s[t] = v;
    __syncthreads();
#pragma unroll
    for (int off = 1; off < SCAN_B; off <<= 1) {
        int u = (t >= off) ? s[t - off] : 0;
        __syncthreads();
        s[t] += u;
        __syncthreads();
    }
    if (i < NNODES) g_cnt[adj * NNODES + i] = s[t] - v;
    if (t == SCAN_B - 1) g_blksum[adj * BLK_PER_ADJ + blk] = s[t];
}

__global__ __launch_bounds__(512) void scanB_kernel() {
    __shared__ int sb[NADJ * BLK_PER_ADJ];
    int t = threadIdx.x;
    for (int i = t; i < NADJ * BLK_PER_ADJ; i += blockDim.x) sb[i] = g_blksum[i];
    __syncthreads();
    if (t < NADJ) {
        int run = 0;
        for (int k = 0; k < BLK_PER_ADJ; k++) {
            int v = sb[t * BLK_PER_ADJ + k];
            sb[t * BLK_PER_ADJ + k] = run;
            run += v;
        }
        g_rowptr[t * (NNODES + 1) + NNODES] = run;
    }
    __syncthreads();
    for (int i = t; i < NADJ * BLK_PER_ADJ; i += blockDim.x) g_blksum[i] = sb[i];
}

__global__ __launch_bounds__(SCAN_B) void scanC_kernel() {
    int bx = blockIdx.x;
    int adj = bx / BLK_PER_ADJ;
    int blk = bx % BLK_PER_ADJ;
    int t = threadIdx.x;
    int i = blk * SCAN_B + t;
    if (i >= NNODES) return;
    int val = g_cnt[adj * NNODES + i] + g_blksum[adj * BLK_PER_ADJ + blk];
    g_rowptr[adj * (NNODES + 1) + i] = val;
    g_cur[adj * NNODES + i] = val;
}

// 4 edges per thread
__global__ void scatter_kernel(const int4* __restrict__ rows4,
                               const int4* __restrict__ cols4,
                               const float4* __restrict__ vals4) {
    int i = blockIdx.x * blockDim.x + threadIdx.x;
    if (i >= NADJ * NEDGE / 4) return;
    int adj = (i * 4) / NEDGE;
    if (!g_used[adj]) return;
    int4 r = __ldg(rows4 + i);
    int4 c = __ldg(cols4 + i);
    float4 v = __ldg(vals4 + i);
    int* cur = g_cur + adj * NNODES;
    int2* ed = (int2*)(g_edge + (size_t)adj * NEDGE);
    int p0 = atomicAdd(cur + r.x, 1);
    ed[p0] = make_int2(c.x, __float_as_int(v.x));
    int p1 = atomicAdd(cur + r.y, 1);
    ed[p1] = make_int2(c.y, __float_as_int(v.y));
    int p2 = atomicAdd(cur + r.z, 1);
    ed[p2] = make_int2(c.z, __float_as_int(v.z));
    int p3 = atomicAdd(cur + r.w, 1);
    ed[p3] = make_int2(c.w, __float_as_int(v.w));
}

// ---------------- bf16-split tensor-core GEMM (3 passes), fp16 output -----
// C[m][n] = sum_k A[m][k] * W[n][k] + bias[n]
// A,W split into bf16 hi + lo; passes: hi*hi + hi*lo + lo*hi (lo*lo ~2^-16, dropped)
#define GBM 128
#define GBN 128
#define GBK 16
#define SPB 24   // bf16 elements per smem row (12 words: 12g+t4 distinct mod 32)

__device__ __forceinline__ void mma_bf16(float* d, const unsigned* a,
                                         unsigned b0, unsigned b1) {
    asm volatile(
        "mma.sync.aligned.m16n8k16.row.col.f32.bf16.bf16.f32 "
        "{%0,%1,%2,%3}, {%4,%5,%6,%7}, {%8,%9}, {%0,%1,%2,%3};"
        : "+f"(d[0]), "+f"(d[1]), "+f"(d[2]), "+f"(d[3])
        : "r"(a[0]), "r"(a[1]), "r"(a[2]), "r"(a[3]),
          "r"(b0), "r"(b1));
}

__device__ __forceinline__ void split_bf16(float x, __nv_bfloat16& h, __nv_bfloat16& l) {
    h = __float2bfloat16(x);
    l = __float2bfloat16(x - __bfloat162float(h));
}

__global__ __launch_bounds__(256) void gemm_bf16_kernel(
    const float* __restrict__ A, const float* __restrict__ W,
    const float* __restrict__ bias, __half* __restrict__ C) {
    __shared__ __nv_bfloat16 As_hi[GBM][SPB];
    __shared__ __nv_bfloat16 As_lo[GBM][SPB];
    __shared__ __nv_bfloat16 Bs_hi[GBN][SPB];
    __shared__ __nv_bfloat16 Bs_lo[GBN][SPB];

    int t = threadIdx.x;
    int m0 = blockIdx.x * GBM;
    int n0 = blockIdx.y * GBN;
    int ws = t >> 5, lane = t & 31;
    int wm = ws & 3, wn = ws >> 2;      // 4 warps along M, 2 along N
    int g = lane >> 2, t4 = lane & 3;

    float acc[2][8][4];
#pragma unroll
    for (int i = 0; i < 2; i++)
#pragma unroll
        for (int j = 0; j < 8; j++)
#pragma unroll
            for (int q = 0; q < 4; q++) acc[i][j][q] = 0.f;

    for (int k0 = 0; k0 < NH; k0 += GBK) {
        // A tile 128x16: 512 float4; 2 per thread
#pragma unroll
        for (int L = 0; L < 2; L++) {
            int f = t + L * 256;
            int m = f >> 2, c4 = f & 3;
            int gm = m0 + m;
            float4 v = make_float4(0.f, 0.f, 0.f, 0.f);
            if (gm < NNODES)
                v = *(const float4*)(A + (size_t)gm * NH + k0 + c4 * 4);
            __nv_bfloat16 h0, l0, h1, l1, h2, l2, h3, l3;
            split_bf16(v.x, h0, l0); split_bf16(v.y, h1, l1);
            split_bf16(v.z, h2, l2); split_bf16(v.w, h3, l3);
            *(__nv_bfloat162*)&As_hi[m][c4 * 4]     = __nv_bfloat162(h0, h1);
            *(__nv_bfloat162*)&As_hi[m][c4 * 4 + 2] = __nv_bfloat162(h2, h3);
            *(__nv_bfloat162*)&As_lo[m][c4 * 4]     = __nv_bfloat162(l0, l1);
            *(__nv_bfloat162*)&As_lo[m][c4 * 4 + 2] = __nv_bfloat162(l2, l3);
        }
        // B tile: Bs[n][k] = W[n0+n][k0+k]
#pragma unroll
        for (int L = 0; L < 2; L++) {
            int f = t + L * 256;
            int n = f >> 2, c4 = f & 3;
            float4 v = *(const float4*)(W + (size_t)(n0 + n) * NH + k0 + c4 * 4);
            __nv_bfloat16 h0, l0, h1, l1, h2, l2, h3, l3;
            split_bf16(v.x, h0, l0); split_bf16(v.y, h1, l1);
            split_bf16(v.z, h2, l2); split_bf16(v.w, h3, l3);
            *(__nv_bfloat162*)&Bs_hi[n][c4 * 4]     = __nv_bfloat162(h0, h1);
            *(__nv_bfloat162*)&Bs_hi[n][c4 * 4 + 2] = __nv_bfloat162(h2, h3);
            *(__nv_bfloat162*)&Bs_lo[n][c4 * 4]     = __nv_bfloat162(l0, l1);
            *(__nv_bfloat162*)&Bs_lo[n][c4 * 4 + 2] = __nv_bfloat162(l2, l3);
        }
        __syncthreads();

        // one k16 MMA step per tile
        unsigned a_hi[2][4], a_lo[2][4];
#pragma unroll
        for (int i = 0; i < 2; i++) {
            int mr = wm * 32 + i * 16;
            a_hi[i][0] = *(const unsigned*)&As_hi[mr + g][t4 * 2];
            a_hi[i][1] = *(const unsigned*)&As_hi[mr + g + 8][t4 * 2];
            a_hi[i][2] = *(const unsigned*)&As_hi[mr + g][t4 * 2 + 8];
            a_hi[i][3] = *(const unsigned*)&As_hi[mr + g + 8][t4 * 2 + 8];
            a_lo[i][0] = *(const unsigned*)&As_lo[mr + g][t4 * 2];
            a_lo[i][1] = *(const unsigned*)&As_lo[mr + g + 8][t4 * 2];
            a_lo[i][2] = *(const unsigned*)&As_lo[mr + g][t4 * 2 + 8];
            a_lo[i][3] = *(const unsigned*)&As_lo[mr + g + 8][t4 * 2 + 8];
        }
#pragma unroll
        for (int j = 0; j < 8; j++) {
            int nb = wn * 64 + j * 8;
            unsigned b_h0 = *(const unsigned*)&Bs_hi[nb + g][t4 * 2];
            unsigned b_h1 = *(const unsigned*)&Bs_hi[nb + g][t4 * 2 + 8];
            unsigned b_l0 = *(const unsigned*)&Bs_lo[nb + g][t4 * 2];
            unsigned b_l1 = *(const unsigned*)&Bs_lo[nb + g][t4 * 2 + 8];
#pragma unroll
            for (int i = 0; i < 2; i++) {
                mma_bf16(acc[i][j], a_hi[i], b_h0, b_h1);
                mma_bf16(acc[i][j], a_hi[i], b_l0, b_l1);
                mma_bf16(acc[i][j], a_lo[i], b_h0, b_h1);
            }
        }
        __syncthreads();
    }

    // epilogue: + bias, convert to fp16, store half2
#pragma unroll
    for (int j = 0; j < 8; j++) {
        int c = n0 + wn * 64 + j * 8 + 2 * t4;
        float bx = __ldg(bias + c);
        float by = __ldg(bias + c + 1);
#pragma unroll
        for (int i = 0; i < 2; i++) {
            int r0 = m0 + wm * 32 + i * 16 + g;
            if (r0 < NNODES) {
                *(half2*)(C + (size_t)r0 * NH + c) =
                    __floats2half2_rn(acc[i][j][0] + bx, acc[i][j][1] + by);
            }
            int r1 = r0 + 8;
            if (r1 < NNODES) {
                *(half2*)(C + (size_t)r1 * NH + c) =
                    __floats2half2_rn(acc[i][j][2] + bx, acc[i][j][3] + by);
            }
        }
    }
}

// ---------------- CSR SpMM primitives -------------------------------------
// Each lane owns 8 consecutive cols (lane*8 .. lane*8+7) = one uint4 of halves.
__device__ __forceinline__ void accum8(float* acc, uint4 pv, float v) {
    const __half2* h = (const __half2*)&pv;
    float2 f0 = __half22float2(h[0]);
    float2 f1 = __half22float2(h[1]);
    float2 f2 = __half22float2(h[2]);
    float2 f3 = __half22float2(h[3]);
    acc[0] += v * f0.x; acc[1] += v * f0.y;
    acc[2] += v * f1.x; acc[3] += v * f1.y;
    acc[4] += v * f2.x; acc[5] += v * f2.y;
    acc[6] += v * f3.x; acc[7] += v * f3.y;
}

// 8-edge unrolled gather: 8 independent 512B row reads in flight per iteration
__device__ __forceinline__ void spmm_row(float* acc, int w, int lane,
                                         const __half* __restrict__ src, int selpos) {
    int adj = g_adj_idx[selpos];
    const int* rp = g_rowptr + adj * (NNODES + 1);
    int beg = __ldg(rp + w), end = __ldg(rp + w + 1);
    const int2* ed = g_edge + (size_t)adj * NEDGE;
    int e = beg;
    // prologue: align e to even index so int4 edge loads are 16B-aligned
    if ((e & 1) && e < end) {
        int2 ev = __ldg(ed + e);
        uint4 pv = __ldg((const uint4*)(src + (size_t)ev.x * NH) + lane);
        accum8(acc, pv, __int_as_float(ev.y));
        e++;
    }
    for (; e + 8 <= end; e += 8) {
        int4 ea = __ldg((const int4*)(ed + e));
        int4 eb = __ldg((const int4*)(ed + e) + 1);
        int4 ec = __ldg((const int4*)(ed + e) + 2);
        int4 eD = __ldg((const int4*)(ed + e) + 3);
        uint4 v0 = __ldg((const uint4*)(src + (size_t)ea.x * NH) + lane);
        uint4 v1 = __ldg((const uint4*)(src + (size_t)ea.z * NH) + lane);
        uint4 v2 = __ldg((const uint4*)(src + (size_t)eb.x * NH) + lane);
        uint4 v3 = __ldg((const uint4*)(src + (size_t)eb.z * NH) + lane);
        uint4 v4 = __ldg((const uint4*)(src + (size_t)ec.x * NH) + lane);
        uint4 v5 = __ldg((const uint4*)(src + (size_t)ec.z * NH) + lane);
        uint4 v6 = __ldg((const uint4*)(src + (size_t)eD.x * NH) + lane);
        uint4 v7 = __ldg((const uint4*)(src + (size_t)eD.z * NH) + lane);
        accum8(acc, v0, __int_as_float(ea.y));
        accum8(acc, v1, __int_as_float(ea.w));
        accum8(acc, v2, __int_as_float(eb.y));
        accum8(acc, v3, __int_as_float(eb.w));
        accum8(acc, v4, __int_as_float(ec.y));
        accum8(acc, v5, __int_as_float(ec.w));
        accum8(acc, v6, __int_as_float(eD.y));
        accum8(acc, v7, __int_as_float(eD.w));
    }
    for (; e + 2 <= end; e += 2) {
        int4 ea = __ldg((const int4*)(ed + e));
        uint4 v0 = __ldg((const uint4*)(src + (size_t)ea.x * NH) + lane);
        uint4 v1 = __ldg((const uint4*)(src + (size_t)ea.z * NH) + lane);
        accum8(acc, v0, __int_as_float(ea.y));
        accum8(acc, v1, __int_as_float(ea.w));
    }
    for (; e < end; e++) {
        int2 ev = __ldg(ed + e);
        uint4 pv = __ldg((const uint4*)(src + (size_t)ev.x * NH) + lane);
        accum8(acc, pv, __int_as_float(ev.y));
    }
}

__device__ __forceinline__ void store_row_h(float* acc, __half* __restrict__ dst,
                                            int w, int lane) {
    uint4 pk;
    half2* ph = (half2*)&pk;
    ph[0] = __floats2half2_rn(acc[0], acc[1]);
    ph[1] = __floats2half2_rn(acc[2], acc[3]);
    ph[2] = __floats2half2_rn(acc[4], acc[5]);
    ph[3] = __floats2half2_rn(acc[6], acc[7]);
    ((uint4*)(dst + (size_t)w * NH))[lane] = pk;
}

// dst = adjA@srcA                          (NSRC==1)
// dst = adjA@srcA + adjB@srcB              (NSRC==2)
template <int NSRC>
__global__ __launch_bounds__(256) void spmm_kernel(
    const __half* __restrict__ srcA, int selA,
    const __half* __restrict__ srcB, int selB,
    __half* __restrict__ dst) {
    int w = (blockIdx.x * blockDim.x + threadIdx.x) >> 5;
    int lane = threadIdx.x & 31;
    if (w >= NNODES) return;
    float acc[8];
#pragma unroll
    for (int i = 0; i < 8; i++) acc[i] = 0.f;
    spmm_row(acc, w, lane, srcA, selA);
    if (NSRC >= 2) spmm_row(acc, w, lane, srcB, selB);
    store_row_h(acc, dst, w, lane);
}

// out = GELU(LN(adjA@srcA + adjB@srcB + adjC@srcC))
__global__ __launch_bounds__(256) void spmm3_ln_gelu_kernel(
    const __half* __restrict__ srcA, int selA,
    const __half* __restrict__ srcB, int selB,
    const __half* __restrict__ srcC, int selC,
    const float* __restrict__ gamma, const float* __restrict__ beta,
    float* __restrict__ out) {
    int w = (blockIdx.x * blockDim.x + threadIdx.x) >> 5;
    int lane = threadIdx.x & 31;
    if (w >= NNODES) return;
    float acc[8];
#pragma unroll
    for (int i = 0; i < 8; i++) acc[i] = 0.f;
    spmm_row(acc, w, lane, srcA, selA);
    spmm_row(acc, w, lane, srcB, selB);
    spmm_row(acc, w, lane, srcC, selC);

    float sum = 0.f, sq = 0.f;
#pragma unroll
    for (int i = 0; i < 8; i++) { sum += acc[i]; sq += acc[i] * acc[i]; }
#pragma unroll
    for (int off = 16; off >= 1; off >>= 1) {
        sum += __shfl_xor_sync(0xFFFFFFFFu, sum, off);
        sq  += __shfl_xor_sync(0xFFFFFFFFu, sq, off);
    }
    float mean = sum * (1.f / NH);
    float var = sq * (1.f / NH) - mean * mean;
    float inv = rsqrtf(var + LN_EPS);

    const float4* g4 = (const float4*)gamma;
    const float4* b4 = (const float4*)beta;
    float4 ga = __ldg(g4 + lane * 2), gb = __ldg(g4 + lane * 2 + 1);
    float4 ba = __ldg(b4 + lane * 2), bb = __ldg(b4 + lane * 2 + 1);
    float gs[8] = {ga.x, ga.y, ga.z, ga.w, gb.x, gb.y, gb.z, gb.w};
    float bs[8] = {ba.x, ba.y, ba.z, ba.w, bb.x, bb.y, bb.z, bb.w};
    float r[8];
#pragma unroll
    for (int i = 0; i < 8; i++) {
        float y = (acc[i] - mean) * inv * gs[i] + bs[i];
        r[i] = 0.5f * y * (1.f + erff(y * 0.70710678118654752f));
    }
    float4* o4 = (float4*)(out + (size_t)w * NH);
    o4[lane * 2] = make_float4(r[0], r[1], r[2], r[3]);
    o4[lane * 2 + 1] = make_float4(r[4], r[5], r[6], r[7]);
}

// ---------------- launch ---------------------------------------------
extern "C" void kernel_launch(void* const* d_in, const int* in_sizes, int n_in,
                              void* d_out, int out_size) {
    const float* x    = (const float*)d_in[0];
    const int* rows   = (const int*)d_in[1];
    const int* cols   = (const int*)d_in[2];
    const float* vals = (const float*)d_in[3];
    const int* seqr   = (const int*)d_in[4];
    const int* resr   = (const int*)d_in[5];
    const float* W    = (const float*)d_in[6];
    const float* b    = (const float*)d_in[7];
    const float* gamma = (const float*)d_in[8];
    const float* beta  = (const float*)d_in[9];
    float* out = (float*)d_out;

    static __half *s0p = nullptr, *s1p, *s2p;
    static cudaStream_t st2;
    static cudaEvent_t evFork, evGemm;
    if (!s0p) {
        cudaGetSymbolAddress((void**)&s0p, g_state0);
        cudaGetSymbolAddress((void**)&s1p, g_state1);
        cudaGetSymbolAddress((void**)&s2p, g_state2);
        cudaStreamCreateWithFlags(&st2, cudaStreamNonBlocking);
        cudaEventCreateWithFlags(&evFork, cudaEventDisableTiming);
        cudaEventCreateWithFlags(&evGemm, cudaEventDisableTiming);
    }

    const int spmm_blocks = (NNODES + 7) / 8;  // warp per row, 8 warps/block
    const int e4_blocks = (NADJ * NEDGE / 4 + 255) / 256;

    // fork: GEMM on st2 runs concurrently with the CSR build chain
    cudaEventRecord(evFork, 0);
    cudaStreamWaitEvent(st2, evFork, 0);
    gemm_bf16_kernel<<<dim3((NNODES + GBM - 1) / GBM, NH / GBN), 256, 0, st2>>>(x, W, b, s0p);
    cudaEventRecord(evGemm, st2);

    // CSR build on the main (captured) stream
    decode_idx_kernel<<<1, 1>>>(seqr, resr);
    zero_cnt_kernel<<<(NADJ * NNODES + 255) / 256, 256>>>();
    hist_kernel<<<e4_blocks, 256>>>((const int4*)rows);
    scanA_kernel<<<NADJ * BLK_PER_ADJ, SCAN_B>>>();
    scanB_kernel<<<1, 512>>>();
    scanC_kernel<<<NADJ * BLK_PER_ADJ, SCAN_B>>>();
    scatter_kernel<<<e4_blocks, 256>>>((const int4*)rows, (const int4*)cols,
                                       (const float4*)vals);

    // join: chain needs both GEMM output and CSR
    cudaStreamWaitEvent(0, evGemm, 0);

    // s1 = seq0@s0
    spmm_kernel<1><<<spmm_blocks, 256>>>(s0p, 0, nullptr, 0, s1p);
    // s2 = seq1@s1 + res0@s0
    spmm_kernel<2><<<spmm_blocks, 256>>>(s1p, 1, s0p, 3, s2p);
    // out = GELU(LN(seq2@s2 + res1@s0 + res2@s1))
    spmm3_ln_gelu_kernel<<<spmm_blocks, 256>>>(s2p, 2, s0p, 4, s1p, 5, gamma, beta, out);
}